// round 3
// baseline (speedup 1.0000x reference)
#include <cuda_runtime.h>
#include <cstdint>

// Problem constants
#define NS      16
#define N_ATOMS 2000
#define NB      2000
#define NA      4000
#define NVV     400000
#define NT      6000
#define NI      1000

// Output row layout (per sample), total 819001 floats
#define OFF_EBOND   0
#define OFF_EANGLE  2000
#define OFF_EUB     6000
#define OFF_EVDW    6001
#define OFF_ECHG    406001
#define OFF_ETOR    806001
#define OFF_EIMP    812001
#define OFF_FORCE   813001
#define ROW         819001

#define K2C_HALF 1.8222615f   // CHARGE/10

// Fused kernel decomposition
#define VDW_CHUNKS   40
#define VDW_CHUNK    (NVV / VDW_CHUNKS)     // 10000
#define VDW_BLOCKS   (VDW_CHUNKS * NS)      // 640
#define BONDED_HALVES 2
#define BONDED_BLOCKS (NS * BONDED_HALVES)  // 32
#define TOTAL_BLOCKS (VDW_BLOCKS + BONDED_BLOCKS)
#define NTHREADS     256
#define BONDED_TOTAL 13000                  // 2000 bond + 4000 angle + 6000 torsion + 1000 imptors

// Per-pair sample-invariant coefficients: {sigma^6, eps, cc, unused}
__device__ float4 g_pair_coef[NVV];

// ---------------------------------------------------------------------------
// Precompute sample-invariant pair chemistry (runs once per launch, ~5us)
// ---------------------------------------------------------------------------
__global__ void precompute_kernel(const int* __restrict__ nonbonded,
                                  const float2* __restrict__ paras_vdw,
                                  const float* __restrict__ paras_charge,
                                  const float* __restrict__ vdw14,
                                  const float* __restrict__ charge14) {
    int p = blockIdx.x * blockDim.x + threadIdx.x;
    if (p >= NVV) return;
    int i = nonbonded[p];
    int j = nonbonded[NVV + p];
    float2 pvi = paras_vdw[i];
    float2 pvj = paras_vdw[j];
    float sigma = pvi.x + pvj.x;
    float s2 = sigma * sigma;
    float s6 = s2 * s2 * s2;
    float eps = (pvi.y * 0.1f) * (pvj.y * 0.1f) * vdw14[p];
    float cc  = (K2C_HALF * paras_charge[i]) * (K2C_HALF * paras_charge[j]) * charge14[p];
    g_pair_coef[p] = make_float4(s6, eps, cc, 0.0f);
}

// ---------------------------------------------------------------------------
// Zero the Force region and E_ub
// ---------------------------------------------------------------------------
__global__ void zero_kernel(float* __restrict__ out) {
    int idx = blockIdx.x * blockDim.x + threadIdx.x;
    const int total = NS * (3 * N_ATOMS + 1);
    if (idx >= total) return;
    int s = idx / (3 * N_ATOMS + 1);
    int k = idx % (3 * N_ATOMS + 1);
    size_t base = (size_t)s * ROW;
    if (k < 3 * N_ATOMS)
        out[base + OFF_FORCE + k] = 0.0f;
    else
        out[base + OFF_EUB] = 0.0f;
}

// ---------------------------------------------------------------------------
// Fused everything kernel.
//   blocks [0, 640): vdw+charge, (sample, chunk), 2-replica smem force accum
//   blocks [640, 672): bonded terms (bond/angle/torsion/imptors), (sample, half)
// ---------------------------------------------------------------------------
__global__ __launch_bounds__(NTHREADS)
void fused_kernel(const float* __restrict__ length_bond,
                  const float* __restrict__ theta_angle,
                  const float* __restrict__ length_vdw,
                  const float* __restrict__ sin_cos_torsion,
                  const float* __restrict__ cos2_imptors,
                  const float2* __restrict__ paras_bond,
                  const float2* __restrict__ paras_angle,
                  const float4* __restrict__ paras_torsion,
                  const float* __restrict__ paras_imptors,
                  const float* __restrict__ dlength_bond,
                  const float* __restrict__ dtheta_angle,
                  const float* __restrict__ dlength_vdw,
                  const float* __restrict__ dtheta_torsion,
                  const float* __restrict__ dcos2_imptors,
                  const int2*  __restrict__ bond_index,
                  const int*   __restrict__ angle_index,
                  const int2*  __restrict__ nbindex,
                  const int4*  __restrict__ torsion_index,
                  const int4*  __restrict__ imptors_index,
                  float* __restrict__ out) {
    __shared__ float sF[2 * 3 * N_ATOMS];   // 48 KB; bonded path uses first half

    const int bx = blockIdx.x;

    if (bx < VDW_BLOCKS) {
        // ================= vdW + charge =================
        const int s     = bx / VDW_CHUNKS;
        const int chunk = bx % VDW_CHUNKS;
        const int c0    = chunk * VDW_CHUNK;

        for (int k = threadIdx.x; k < 2 * 3 * N_ATOMS; k += NTHREADS) sF[k] = 0.0f;
        __syncthreads();

        // replica split: warps 0-3 -> sFr[0..], warps 4-7 -> sFr[6000..]
        float* sFr = sF + ((threadIdx.x >> 7) & 1) * (3 * N_ATOMS);

        const float* Lrow = length_vdw + (size_t)s * NVV;
        const float* Drow = dlength_vdw + (size_t)s * NVV * 6;
        size_t base = (size_t)s * ROW;
        float* Ev = out + base + OFF_EVDW;
        float* Ec = out + base + OFF_ECHG;

        for (int p = c0 + threadIdx.x; p < c0 + VDW_CHUNK; p += NTHREADS) {
            float4 pc = g_pair_coef[p];       // {s6, eps, cc, -}

            float r   = Lrow[p];
            float ir  = __fdividef(1.0f, r);
            float ir2 = ir * ir;
            float t   = pc.x * (ir2 * ir2 * ir2);

            Ev[p] = pc.y * (t * t - 2.0f * t);
            Ec[p] = pc.z * ir;

            float w = 12.0f * pc.y * t * (1.0f - t) * ir - pc.z * ir2;

            const float2* D = (const float2*)(Drow + (size_t)p * 6);
            float2 d0 = D[0], d1 = D[1], d2 = D[2];
            int2 ab = nbindex[p];
            atomicAdd(&sFr[ab.x * 3 + 0], d0.x * w);
            atomicAdd(&sFr[ab.x * 3 + 1], d0.y * w);
            atomicAdd(&sFr[ab.x * 3 + 2], d1.x * w);
            atomicAdd(&sFr[ab.y * 3 + 0], d1.y * w);
            atomicAdd(&sFr[ab.y * 3 + 1], d2.x * w);
            atomicAdd(&sFr[ab.y * 3 + 2], d2.y * w);
        }
        __syncthreads();

        float* F = out + base + OFF_FORCE;
        for (int k = threadIdx.x; k < 3 * N_ATOMS; k += NTHREADS) {
            float v = sF[k] + sF[3 * N_ATOMS + k];
            if (v != 0.0f) atomicAdd(&F[k], v);
        }
    } else {
        // ================= bonded terms =================
        const int bid  = bx - VDW_BLOCKS;
        const int s    = bid / BONDED_HALVES;
        const int half = bid % BONDED_HALVES;
        const int e0   = half * (BONDED_TOTAL / BONDED_HALVES);
        const int e1   = e0 + (BONDED_TOTAL / BONDED_HALVES);

        for (int k = threadIdx.x; k < 3 * N_ATOMS; k += NTHREADS) sF[k] = 0.0f;
        __syncthreads();

        size_t base = (size_t)s * ROW;

        for (int e = e0 + threadIdx.x; e < e1; e += NTHREADS) {
            if (e < 2000) {
                // ---- bond ----
                int b = e;
                float2 pb = paras_bond[b];
                float K = pb.x * 100.0f;
                float d = length_bond[(size_t)s * NB + b] - pb.y;
                out[base + OFF_EBOND + b] = K * d * d;
                float Fs = 2.0f * K * d;
                const float2* D = (const float2*)(dlength_bond + ((size_t)s * NB + b) * 6);
                float2 d0 = D[0], d1 = D[1], d2 = D[2];
                int2 ab = bond_index[b];
                atomicAdd(&sF[ab.x * 3 + 0], d0.x * Fs);
                atomicAdd(&sF[ab.x * 3 + 1], d0.y * Fs);
                atomicAdd(&sF[ab.x * 3 + 2], d1.x * Fs);
                atomicAdd(&sF[ab.y * 3 + 0], d1.y * Fs);
                atomicAdd(&sF[ab.y * 3 + 1], d2.x * Fs);
                atomicAdd(&sF[ab.y * 3 + 2], d2.y * Fs);
            } else if (e < 6000) {
                // ---- angle ----
                int a = e - 2000;
                float2 pa = paras_angle[a];
                float Ka  = pa.x * 10.0f;
                float th0 = pa.y * 0.3141592653589793f;
                float da  = theta_angle[(size_t)s * NA + a] - th0;
                out[base + OFF_EANGLE + a] = Ka * da * da;
                float Fs = 2.0f * Ka * da;
                const float* D = dtheta_angle + ((size_t)s * NA + a) * 9;
                #pragma unroll
                for (int k = 0; k < 3; k++) {
                    int atom = angle_index[a * 3 + k];
                    #pragma unroll
                    for (int c = 0; c < 3; c++)
                        atomicAdd(&sF[atom * 3 + c], D[k * 3 + c] * Fs);
                }
            } else if (e < 12000) {
                // ---- torsion ----
                int t = e - 6000;
                const float4* SC = (const float4*)(sin_cos_torsion + ((size_t)s * NT + t) * 8);
                float4 sc0 = SC[0];   // sin1, cos1, sin2, cos2
                float4 sc1 = SC[1];   // sin3, cos3, sin4, cos4
                float4 p = paras_torsion[t];
                float E = sc0.y * p.x + sc0.w * p.y + sc1.y * p.z + sc1.w * p.w;
                out[base + OFF_ETOR + t] = E;
                float Fs = -(sc0.x * p.x + sc0.z * (2.0f * p.y) +
                             sc1.x * (3.0f * p.z) + sc1.z * (4.0f * p.w));
                const float4* D = (const float4*)(dtheta_torsion + ((size_t)s * NT + t) * 12);
                float4 dA = D[0], dB = D[1], dC = D[2];
                int4 ti = torsion_index[t];
                atomicAdd(&sF[ti.x * 3 + 0], dA.x * Fs);
                atomicAdd(&sF[ti.x * 3 + 1], dA.y * Fs);
                atomicAdd(&sF[ti.x * 3 + 2], dA.z * Fs);
                atomicAdd(&sF[ti.y * 3 + 0], dA.w * Fs);
                atomicAdd(&sF[ti.y * 3 + 1], dB.x * Fs);
                atomicAdd(&sF[ti.y * 3 + 2], dB.y * Fs);
                atomicAdd(&sF[ti.z * 3 + 0], dB.z * Fs);
                atomicAdd(&sF[ti.z * 3 + 1], dB.w * Fs);
                atomicAdd(&sF[ti.z * 3 + 2], dC.x * Fs);
                atomicAdd(&sF[ti.w * 3 + 0], dC.y * Fs);
                atomicAdd(&sF[ti.w * 3 + 1], dC.z * Fs);
                atomicAdd(&sF[ti.w * 3 + 2], dC.w * Fs);
            } else {
                // ---- imptors ----
                int i = e - 12000;
                float ki = paras_imptors[i];
                out[base + OFF_EIMP + i] = ki * (1.0f - cos2_imptors[(size_t)s * NI + i]);
                float Fs = -ki;
                const float4* D = (const float4*)(dcos2_imptors + ((size_t)s * NI + i) * 12);
                float4 dA = D[0], dB = D[1], dC = D[2];
                int4 ii = imptors_index[i];
                atomicAdd(&sF[ii.x * 3 + 0], dA.x * Fs);
                atomicAdd(&sF[ii.x * 3 + 1], dA.y * Fs);
                atomicAdd(&sF[ii.x * 3 + 2], dA.z * Fs);
                atomicAdd(&sF[ii.y * 3 + 0], dA.w * Fs);
                atomicAdd(&sF[ii.y * 3 + 1], dB.x * Fs);
                atomicAdd(&sF[ii.y * 3 + 2], dB.y * Fs);
                atomicAdd(&sF[ii.z * 3 + 0], dB.z * Fs);
                atomicAdd(&sF[ii.z * 3 + 1], dB.w * Fs);
                atomicAdd(&sF[ii.z * 3 + 2], dC.x * Fs);
                atomicAdd(&sF[ii.w * 3 + 0], dC.y * Fs);
                atomicAdd(&sF[ii.w * 3 + 1], dC.z * Fs);
                atomicAdd(&sF[ii.w * 3 + 2], dC.w * Fs);
            }
        }
        __syncthreads();

        float* F = out + base + OFF_FORCE;
        for (int k = threadIdx.x; k < 3 * N_ATOMS; k += NTHREADS) {
            float v = sF[k];
            if (v != 0.0f) atomicAdd(&F[k], v);
        }
    }
}

// ---------------------------------------------------------------------------
// Launch
// ---------------------------------------------------------------------------
extern "C" void kernel_launch(void* const* d_in, const int* in_sizes, int n_in,
                              void* d_out, int out_size) {
    const float* length_bond     = (const float*)d_in[0];
    const float* theta_angle     = (const float*)d_in[1];
    const float* length_vdw      = (const float*)d_in[2];
    const float* sin_cos_torsion = (const float*)d_in[3];
    const float* cos2_imptors    = (const float*)d_in[4];
    const float* vdw14           = (const float*)d_in[5];
    const float* charge14        = (const float*)d_in[6];
    const float* paras_bond      = (const float*)d_in[7];
    const float* paras_angle     = (const float*)d_in[8];
    const float* paras_vdw       = (const float*)d_in[9];
    const float* paras_charge    = (const float*)d_in[10];
    const float* paras_torsion   = (const float*)d_in[11];
    const float* paras_imptors   = (const float*)d_in[12];
    const float* dlength_bond    = (const float*)d_in[13];
    const float* dtheta_angle    = (const float*)d_in[14];
    const float* dlength_vdw     = (const float*)d_in[15];
    const float* dtheta_torsion  = (const float*)d_in[16];
    const float* dcos2_imptors   = (const float*)d_in[17];
    const int*   nonbonded       = (const int*)d_in[18];
    const int*   bond_index      = (const int*)d_in[19];
    const int*   angle_index     = (const int*)d_in[20];
    const int*   nonbonded_index = (const int*)d_in[21];
    const int*   torsion_index   = (const int*)d_in[22];
    const int*   imptors_index   = (const int*)d_in[23];
    float* out = (float*)d_out;

    precompute_kernel<<<(NVV + 255) / 256, 256>>>(
        nonbonded, (const float2*)paras_vdw, paras_charge, vdw14, charge14);
    {
        int total = NS * (3 * N_ATOMS + 1);
        zero_kernel<<<(total + 255) / 256, 256>>>(out);
    }
    fused_kernel<<<TOTAL_BLOCKS, NTHREADS>>>(
        length_bond, theta_angle, length_vdw, sin_cos_torsion, cos2_imptors,
        (const float2*)paras_bond, (const float2*)paras_angle,
        (const float4*)paras_torsion, paras_imptors,
        dlength_bond, dtheta_angle, dlength_vdw, dtheta_torsion, dcos2_imptors,
        (const int2*)bond_index, angle_index,
        (const int2*)nonbonded_index, (const int4*)torsion_index,
        (const int4*)imptors_index, out);
}

// round 4
// speedup vs baseline: 1.0169x; 1.0169x over previous
#include <cuda_runtime.h>
#include <cstdint>

// Problem constants
#define NS      16
#define N_ATOMS 2000
#define NB      2000
#define NA      4000
#define NVV     400000
#define NT      6000
#define NI      1000

// Output row layout (per sample), total 819001 floats
#define OFF_EBOND   0
#define OFF_EANGLE  2000
#define OFF_EUB     6000
#define OFF_EVDW    6001
#define OFF_ECHG    406001
#define OFF_ETOR    806001
#define OFF_EIMP    812001
#define OFF_FORCE   813001
#define ROW         819001

#define K2C_HALF 1.8222615f   // CHARGE/10

// Fused kernel decomposition: bonded blocks FIRST (they'd otherwise be the tail)
#define VDW_CHUNKS   25
#define VDW_CHUNK    (NVV / VDW_CHUNKS)     // 16000
#define VDW_BLOCKS   (VDW_CHUNKS * NS)      // 400
#define BONDED_HALVES 2
#define BONDED_BLOCKS (NS * BONDED_HALVES)  // 32
#define TOTAL_BLOCKS (VDW_BLOCKS + BONDED_BLOCKS)
#define NTHREADS     256
#define BONDED_TOTAL 13000                  // 2000 bond + 4000 angle + 6000 torsion + 1000 imptors

// ---------------------------------------------------------------------------
// Zero the Force region and E_ub
// ---------------------------------------------------------------------------
__global__ void zero_kernel(float* __restrict__ out) {
    int idx = blockIdx.x * blockDim.x + threadIdx.x;
    const int total = NS * (3 * N_ATOMS + 1);
    if (idx >= total) return;
    int s = idx / (3 * N_ATOMS + 1);
    int k = idx % (3 * N_ATOMS + 1);
    size_t base = (size_t)s * ROW;
    if (k < 3 * N_ATOMS)
        out[base + OFF_FORCE + k] = 0.0f;
    else
        out[base + OFF_EUB] = 0.0f;
}

// ---------------------------------------------------------------------------
// Fused everything kernel.
//   blocks [0, 32):   bonded terms (bond/angle/torsion/imptors), (sample, half)
//   blocks [32, 432): vdw+charge, (sample, chunk), 2-replica smem force accum
// ---------------------------------------------------------------------------
__global__ __launch_bounds__(NTHREADS)
void fused_kernel(const float* __restrict__ length_bond,
                  const float* __restrict__ theta_angle,
                  const float* __restrict__ length_vdw,
                  const float* __restrict__ sin_cos_torsion,
                  const float* __restrict__ cos2_imptors,
                  const float* __restrict__ vdw14,
                  const float* __restrict__ charge14,
                  const float2* __restrict__ paras_bond,
                  const float2* __restrict__ paras_angle,
                  const float2* __restrict__ paras_vdw,
                  const float* __restrict__ paras_charge,
                  const float4* __restrict__ paras_torsion,
                  const float* __restrict__ paras_imptors,
                  const float* __restrict__ dlength_bond,
                  const float* __restrict__ dtheta_angle,
                  const float* __restrict__ dlength_vdw,
                  const float* __restrict__ dtheta_torsion,
                  const float* __restrict__ dcos2_imptors,
                  const int*   __restrict__ nonbonded,
                  const int2*  __restrict__ bond_index,
                  const int*   __restrict__ angle_index,
                  const int2*  __restrict__ nbindex,
                  const int4*  __restrict__ torsion_index,
                  const int4*  __restrict__ imptors_index,
                  float* __restrict__ out) {
    __shared__ float sF[2 * 3 * N_ATOMS];   // 48 KB; bonded path uses first half

    const int bx = blockIdx.x;

    if (bx >= BONDED_BLOCKS) {
        // ================= vdW + charge =================
        const int vb    = bx - BONDED_BLOCKS;
        const int s     = vb / VDW_CHUNKS;
        const int chunk = vb % VDW_CHUNKS;
        const int c0    = chunk * VDW_CHUNK;

        {
            float4* z = (float4*)sF;
            for (int k = threadIdx.x; k < (2 * 3 * N_ATOMS) / 4; k += NTHREADS)
                z[k] = make_float4(0.f, 0.f, 0.f, 0.f);
        }
        __syncthreads();

        // replica split: warps 0-3 -> sFr[0..], warps 4-7 -> sFr[6000..]
        float* sFr = sF + ((threadIdx.x >> 7) & 1) * (3 * N_ATOMS);

        const float* Lrow = length_vdw + (size_t)s * NVV;
        const float* Drow = dlength_vdw + (size_t)s * NVV * 6;
        size_t base = (size_t)s * ROW;
        float* Ev = out + base + OFF_EVDW;
        float* Ec = out + base + OFF_ECHG;

        // 2 pairs per thread per iteration (vector loads, more MLP)
        for (int p = c0 + 2 * threadIdx.x; p < c0 + VDW_CHUNK; p += 2 * NTHREADS) {
            // streaming loads for the one-touch big arrays
            float2 r2  = __ldcs((const float2*)(Lrow + p));
            const float4* D4 = (const float4*)(Drow + (size_t)p * 6);
            float4 dA = __ldcs(D4 + 0);   // p0: d0x d0y d0z d1x
            float4 dB = __ldcs(D4 + 1);   // p0: d1y d1z | p1: d0x d0y
            float4 dC = __ldcs(D4 + 2);   // p1: d0z d1x d1y d1z
            int4  ij2 = __ldg((const int4*)(nbindex + p));   // {a0,b0,a1,b1}
            float2 v14 = __ldg((const float2*)(vdw14 + p));
            float2 c14 = __ldg((const float2*)(charge14 + p));
            int i0 = __ldg(nonbonded + p);
            int j0 = __ldg(nonbonded + NVV + p);
            int i1 = __ldg(nonbonded + p + 1);
            int j1 = __ldg(nonbonded + NVV + p + 1);

            // ---- pair 0 ----
            {
                float2 pvi = __ldg(paras_vdw + i0);
                float2 pvj = __ldg(paras_vdw + j0);
                float sigma = pvi.x + pvj.x;
                float eps   = pvi.y * pvj.y * 0.01f * v14.x;
                float cc    = (K2C_HALF * __ldg(paras_charge + i0)) *
                              (K2C_HALF * __ldg(paras_charge + j0)) * c14.x;
                float ir  = __fdividef(1.0f, r2.x);
                float ir2 = ir * ir;
                float s2  = sigma * sigma;
                float t   = (s2 * s2 * s2) * (ir2 * ir2 * ir2);
                __stcs(Ev + p, eps * (t * t - 2.0f * t));
                __stcs(Ec + p, cc * ir);
                float w = 12.0f * eps * t * (1.0f - t) * ir - cc * ir2;
                atomicAdd(&sFr[ij2.x * 3 + 0], dA.x * w);
                atomicAdd(&sFr[ij2.x * 3 + 1], dA.y * w);
                atomicAdd(&sFr[ij2.x * 3 + 2], dA.z * w);
                atomicAdd(&sFr[ij2.y * 3 + 0], dA.w * w);
                atomicAdd(&sFr[ij2.y * 3 + 1], dB.x * w);
                atomicAdd(&sFr[ij2.y * 3 + 2], dB.y * w);
            }
            // ---- pair 1 ----
            {
                float2 pvi = __ldg(paras_vdw + i1);
                float2 pvj = __ldg(paras_vdw + j1);
                float sigma = pvi.x + pvj.x;
                float eps   = pvi.y * pvj.y * 0.01f * v14.y;
                float cc    = (K2C_HALF * __ldg(paras_charge + i1)) *
                              (K2C_HALF * __ldg(paras_charge + j1)) * c14.y;
                float ir  = __fdividef(1.0f, r2.y);
                float ir2 = ir * ir;
                float s2  = sigma * sigma;
                float t   = (s2 * s2 * s2) * (ir2 * ir2 * ir2);
                __stcs(Ev + p + 1, eps * (t * t - 2.0f * t));
                __stcs(Ec + p + 1, cc * ir);
                float w = 12.0f * eps * t * (1.0f - t) * ir - cc * ir2;
                atomicAdd(&sFr[ij2.z * 3 + 0], dB.z * w);
                atomicAdd(&sFr[ij2.z * 3 + 1], dB.w * w);
                atomicAdd(&sFr[ij2.z * 3 + 2], dC.x * w);
                atomicAdd(&sFr[ij2.w * 3 + 0], dC.y * w);
                atomicAdd(&sFr[ij2.w * 3 + 1], dC.z * w);
                atomicAdd(&sFr[ij2.w * 3 + 2], dC.w * w);
            }
        }
        __syncthreads();

        float* F = out + base + OFF_FORCE;
        for (int k = threadIdx.x; k < 3 * N_ATOMS; k += NTHREADS) {
            float v = sF[k] + sF[3 * N_ATOMS + k];
            if (v != 0.0f) atomicAdd(&F[k], v);
        }
    } else {
        // ================= bonded terms =================
        const int s    = bx / BONDED_HALVES;
        const int half = bx % BONDED_HALVES;
        const int e0   = half * (BONDED_TOTAL / BONDED_HALVES);
        const int e1   = e0 + (BONDED_TOTAL / BONDED_HALVES);

        {
            float4* z = (float4*)sF;
            for (int k = threadIdx.x; k < (3 * N_ATOMS) / 4; k += NTHREADS)
                z[k] = make_float4(0.f, 0.f, 0.f, 0.f);
        }
        __syncthreads();

        size_t base = (size_t)s * ROW;

        for (int e = e0 + threadIdx.x; e < e1; e += NTHREADS) {
            if (e < 2000) {
                // ---- bond ----
                int b = e;
                float2 pb = paras_bond[b];
                float K = pb.x * 100.0f;
                float d = length_bond[(size_t)s * NB + b] - pb.y;
                out[base + OFF_EBOND + b] = K * d * d;
                float Fs = 2.0f * K * d;
                const float2* D = (const float2*)(dlength_bond + ((size_t)s * NB + b) * 6);
                float2 d0 = D[0], d1 = D[1], d2 = D[2];
                int2 ab = bond_index[b];
                atomicAdd(&sF[ab.x * 3 + 0], d0.x * Fs);
                atomicAdd(&sF[ab.x * 3 + 1], d0.y * Fs);
                atomicAdd(&sF[ab.x * 3 + 2], d1.x * Fs);
                atomicAdd(&sF[ab.y * 3 + 0], d1.y * Fs);
                atomicAdd(&sF[ab.y * 3 + 1], d2.x * Fs);
                atomicAdd(&sF[ab.y * 3 + 2], d2.y * Fs);
            } else if (e < 6000) {
                // ---- angle ----
                int a = e - 2000;
                float2 pa = paras_angle[a];
                float Ka  = pa.x * 10.0f;
                float th0 = pa.y * 0.3141592653589793f;
                float da  = theta_angle[(size_t)s * NA + a] - th0;
                out[base + OFF_EANGLE + a] = Ka * da * da;
                float Fs = 2.0f * Ka * da;
                const float* D = dtheta_angle + ((size_t)s * NA + a) * 9;
                #pragma unroll
                for (int k = 0; k < 3; k++) {
                    int atom = angle_index[a * 3 + k];
                    #pragma unroll
                    for (int c = 0; c < 3; c++)
                        atomicAdd(&sF[atom * 3 + c], D[k * 3 + c] * Fs);
                }
            } else if (e < 12000) {
                // ---- torsion ----
                int t = e - 6000;
                const float4* SC = (const float4*)(sin_cos_torsion + ((size_t)s * NT + t) * 8);
                float4 sc0 = SC[0];   // sin1, cos1, sin2, cos2
                float4 sc1 = SC[1];   // sin3, cos3, sin4, cos4
                float4 p = paras_torsion[t];
                float E = sc0.y * p.x + sc0.w * p.y + sc1.y * p.z + sc1.w * p.w;
                out[base + OFF_ETOR + t] = E;
                float Fs = -(sc0.x * p.x + sc0.z * (2.0f * p.y) +
                             sc1.x * (3.0f * p.z) + sc1.z * (4.0f * p.w));
                const float4* D = (const float4*)(dtheta_torsion + ((size_t)s * NT + t) * 12);
                float4 dA = D[0], dB = D[1], dC = D[2];
                int4 ti = torsion_index[t];
                atomicAdd(&sF[ti.x * 3 + 0], dA.x * Fs);
                atomicAdd(&sF[ti.x * 3 + 1], dA.y * Fs);
                atomicAdd(&sF[ti.x * 3 + 2], dA.z * Fs);
                atomicAdd(&sF[ti.y * 3 + 0], dA.w * Fs);
                atomicAdd(&sF[ti.y * 3 + 1], dB.x * Fs);
                atomicAdd(&sF[ti.y * 3 + 2], dB.y * Fs);
                atomicAdd(&sF[ti.z * 3 + 0], dB.z * Fs);
                atomicAdd(&sF[ti.z * 3 + 1], dB.w * Fs);
                atomicAdd(&sF[ti.z * 3 + 2], dC.x * Fs);
                atomicAdd(&sF[ti.w * 3 + 0], dC.y * Fs);
                atomicAdd(&sF[ti.w * 3 + 1], dC.z * Fs);
                atomicAdd(&sF[ti.w * 3 + 2], dC.w * Fs);
            } else {
                // ---- imptors ----
                int i = e - 12000;
                float ki = paras_imptors[i];
                out[base + OFF_EIMP + i] = ki * (1.0f - cos2_imptors[(size_t)s * NI + i]);
                float Fs = -ki;
                const float4* D = (const float4*)(dcos2_imptors + ((size_t)s * NI + i) * 12);
                float4 dA = D[0], dB = D[1], dC = D[2];
                int4 ii = imptors_index[i];
                atomicAdd(&sF[ii.x * 3 + 0], dA.x * Fs);
                atomicAdd(&sF[ii.x * 3 + 1], dA.y * Fs);
                atomicAdd(&sF[ii.x * 3 + 2], dA.z * Fs);
                atomicAdd(&sF[ii.y * 3 + 0], dA.w * Fs);
                atomicAdd(&sF[ii.y * 3 + 1], dB.x * Fs);
                atomicAdd(&sF[ii.y * 3 + 2], dB.y * Fs);
                atomicAdd(&sF[ii.z * 3 + 0], dB.z * Fs);
                atomicAdd(&sF[ii.z * 3 + 1], dB.w * Fs);
                atomicAdd(&sF[ii.z * 3 + 2], dC.x * Fs);
                atomicAdd(&sF[ii.w * 3 + 0], dC.y * Fs);
                atomicAdd(&sF[ii.w * 3 + 1], dC.z * Fs);
                atomicAdd(&sF[ii.w * 3 + 2], dC.w * Fs);
            }
        }
        __syncthreads();

        float* F = out + base + OFF_FORCE;
        for (int k = threadIdx.x; k < 3 * N_ATOMS; k += NTHREADS) {
            float v = sF[k];
            if (v != 0.0f) atomicAdd(&F[k], v);
        }
    }
}

// ---------------------------------------------------------------------------
// Launch
// ---------------------------------------------------------------------------
extern "C" void kernel_launch(void* const* d_in, const int* in_sizes, int n_in,
                              void* d_out, int out_size) {
    const float* length_bond     = (const float*)d_in[0];
    const float* theta_angle     = (const float*)d_in[1];
    const float* length_vdw      = (const float*)d_in[2];
    const float* sin_cos_torsion = (const float*)d_in[3];
    const float* cos2_imptors    = (const float*)d_in[4];
    const float* vdw14           = (const float*)d_in[5];
    const float* charge14        = (const float*)d_in[6];
    const float* paras_bond      = (const float*)d_in[7];
    const float* paras_angle     = (const float*)d_in[8];
    const float* paras_vdw       = (const float*)d_in[9];
    const float* paras_charge    = (const float*)d_in[10];
    const float* paras_torsion   = (const float*)d_in[11];
    const float* paras_imptors   = (const float*)d_in[12];
    const float* dlength_bond    = (const float*)d_in[13];
    const float* dtheta_angle    = (const float*)d_in[14];
    const float* dlength_vdw     = (const float*)d_in[15];
    const float* dtheta_torsion  = (const float*)d_in[16];
    const float* dcos2_imptors   = (const float*)d_in[17];
    const int*   nonbonded       = (const int*)d_in[18];
    const int*   bond_index      = (const int*)d_in[19];
    const int*   angle_index     = (const int*)d_in[20];
    const int*   nonbonded_index = (const int*)d_in[21];
    const int*   torsion_index   = (const int*)d_in[22];
    const int*   imptors_index   = (const int*)d_in[23];
    float* out = (float*)d_out;

    {
        int total = NS * (3 * N_ATOMS + 1);
        zero_kernel<<<(total + 255) / 256, 256>>>(out);
    }
    fused_kernel<<<TOTAL_BLOCKS, NTHREADS>>>(
        length_bond, theta_angle, length_vdw, sin_cos_torsion, cos2_imptors,
        vdw14, charge14,
        (const float2*)paras_bond, (const float2*)paras_angle,
        (const float2*)paras_vdw, paras_charge,
        (const float4*)paras_torsion, paras_imptors,
        dlength_bond, dtheta_angle, dlength_vdw, dtheta_torsion, dcos2_imptors,
        nonbonded, (const int2*)bond_index, angle_index,
        (const int2*)nonbonded_index, (const int4*)torsion_index,
        (const int4*)imptors_index, out);
}